// round 2
// baseline (speedup 1.0000x reference)
#include <cuda_runtime.h>
#include <cstdint>

#define N_NODES 20000
#define F_DIM   512
#define S_SUB   6
#define NCOL    1024           // concat(re, im)
#define CHUNKS  200
#define ROWS_PER_CHUNK 100     // 200 * 100 = 20000
#define A_COEF  0.025f         // T * HSCALE
#define BN_EPS  1e-5f

// ---------------- scratch (device globals; no cudaMalloc allowed) ----------
__device__ float g_Y[N_NODES * NCOL];      // complex linear output (re | im)
__device__ float g_Z[N_NODES * NCOL];      // relu(evolved) (re | im)
__device__ float g_Xt[N_NODES * F_DIM];    // tf32-rounded X
__device__ float g_Wre[F_DIM * F_DIM];     // tf32-rounded W_re
__device__ float g_Wim[F_DIM * F_DIM];     // tf32-rounded W_im
__device__ float g_Psum[CHUNKS * NCOL];
__device__ float g_Psq[CHUNKS * NCOL];
__device__ float g_scale[NCOL];
__device__ float g_shift[NCOL];

// ---------------- helpers ---------------------------------------------------
__device__ __forceinline__ float f2tf32f(float x) {
    uint32_t r;
    asm("cvt.rna.tf32.f32 %0, %1;" : "=r"(r) : "f"(x));
    return __uint_as_float(r);
}

__device__ __forceinline__ void mma_tf32(float* c, const uint32_t* a, const uint32_t* b) {
    asm volatile(
        "mma.sync.aligned.m16n8k8.row.col.f32.tf32.tf32.f32 "
        "{%0,%1,%2,%3}, {%4,%5,%6,%7}, {%8,%9}, {%0,%1,%2,%3};"
        : "+f"(c[0]), "+f"(c[1]), "+f"(c[2]), "+f"(c[3])
        : "r"(a[0]), "r"(a[1]), "r"(a[2]), "r"(a[3]), "r"(b[0]), "r"(b[1]));
}

__device__ __forceinline__ void cp16(uint32_t dst, const void* src, int srcbytes) {
    asm volatile("cp.async.cg.shared.global [%0], [%1], 16, %2;"
                 :: "r"(dst), "l"(src), "r"(srcbytes));
}
__device__ __forceinline__ void cp_commit() { asm volatile("cp.async.commit_group;"); }
__device__ __forceinline__ void cp_wait1()  { asm volatile("cp.async.wait_group 1;"); }
__device__ __forceinline__ void cp_wait0()  { asm volatile("cp.async.wait_group 0;"); }

// ---------------- K0: pre-round inputs to tf32 ------------------------------
__global__ __launch_bounds__(256) void k_prep(const float* __restrict__ X,
                                              const float* __restrict__ Wre,
                                              const float* __restrict__ Wim) {
    const int XV = N_NODES * F_DIM / 4;        // 2,560,000 float4
    const int WV = F_DIM * F_DIM / 4;          // 65,536 float4
    const int total = XV + 2 * WV;
    for (int i = blockIdx.x * blockDim.x + threadIdx.x; i < total; i += gridDim.x * blockDim.x) {
        const float4* src; float* dst; int j;
        if (i < XV)            { src = (const float4*)X;   dst = g_Xt;  j = i; }
        else if (i < XV + WV)  { src = (const float4*)Wre; dst = g_Wre; j = i - XV; }
        else                   { src = (const float4*)Wim; dst = g_Wim; j = i - XV - WV; }
        float4 v = src[j];
        v.x = f2tf32f(v.x); v.y = f2tf32f(v.y); v.z = f2tf32f(v.z); v.w = f2tf32f(v.w);
        *(float4*)&dst[(size_t)j * 4] = v;
    }
}

// ---------------- K1: tf32 GEMM, 3-stage cp.async pipeline ------------------
#define BM 128
#define BN 128
#define BK 32
#define NKT (F_DIM / BK)           // 16
#define ASTRIDE 36                 // floats; 144B = 9*16 (16B-aligned rows)
#define BSTRIDE 136                // floats; 544B = 34*16
#define A_FLOATS (BM * ASTRIDE)    // 4608
#define B_FLOATS (BK * BSTRIDE)    // 4352
#define STAGE_FLOATS (A_FLOATS + B_FLOATS)   // 8960
#define GEMM_SMEM (3 * STAGE_FLOATS * 4)     // 107520 bytes

__global__ __launch_bounds__(256) void k_gemm(
    const float* __restrict__ bre, const float* __restrict__ bim)
{
    extern __shared__ float smem[];
    const int tid = threadIdx.x;
    const int bm = blockIdx.x, bn = blockIdx.y;
    const float* W    = (bn < 4) ? g_Wre : g_Wim;
    const float* bias = (bn < 4) ? bre : bim;
    const int colOff  = (bn & 3) * BN;

    const int lane = tid & 31, w = tid >> 5;
    const int wm = w & 1, wn = w >> 1;           // 2x4 warp grid, warp tile 64x32
    const int gID = lane >> 2, tig = lane & 3;

    // loader coordinates
    const int ar = tid >> 3, ac = (tid & 7) * 4;   // A: 32 rows/pass, 4 passes
    const int br = tid >> 5, bc = (tid & 31) * 4;  // B: 8 rows/pass, 4 passes

    uint32_t sbase = (uint32_t)__cvta_generic_to_shared(smem);

    auto issue = [&](int kt, int buf) {
        uint32_t abase = sbase + (buf * STAGE_FLOATS) * 4;
        uint32_t bbase = abase + A_FLOATS * 4;
#pragma unroll
        for (int i = 0; i < 4; i++) {
            int r = ar + i * 32;
            int grow = bm * BM + r;
            int ok = (grow < N_NODES) ? 16 : 0;
            const float* src = &g_Xt[(size_t)min(grow, N_NODES - 1) * F_DIM + kt * BK + ac];
            cp16(abase + (r * ASTRIDE + ac) * 4, src, ok);
        }
#pragma unroll
        for (int i = 0; i < 4; i++) {
            int r = br + i * 8;
            const float* src = &W[(size_t)(kt * BK + r) * F_DIM + colOff + bc];
            cp16(bbase + (r * BSTRIDE + bc) * 4, src, 16);
        }
        cp_commit();
    };

    float acc[4][4][4];
#pragma unroll
    for (int m = 0; m < 4; m++)
#pragma unroll
        for (int n = 0; n < 4; n++)
#pragma unroll
            for (int i = 0; i < 4; i++) acc[m][n][i] = 0.f;

    issue(0, 0);
    issue(1, 1);

    int buf = 0;
#pragma unroll 1
    for (int j = 0; j < NKT; j++) {
        if (j < NKT - 1) cp_wait1(); else cp_wait0();
        __syncthreads();
        if (j + 2 < NKT) {
            int nb = buf + 2; if (nb >= 3) nb -= 3;
            issue(j + 2, nb);
        }
        const float* As = smem + buf * STAGE_FLOATS;
        const float* Bs = As + A_FLOATS;
#pragma unroll
        for (int k8 = 0; k8 < 4; k8++) {
            const int kk = k8 * 8;
            uint32_t afr[4][4], bfr[4][2];
#pragma unroll
            for (int m = 0; m < 4; m++) {
                int row = wm * 64 + m * 16;
                afr[m][0] = __float_as_uint(As[(row + gID) * ASTRIDE + kk + tig]);
                afr[m][1] = __float_as_uint(As[(row + gID + 8) * ASTRIDE + kk + tig]);
                afr[m][2] = __float_as_uint(As[(row + gID) * ASTRIDE + kk + tig + 4]);
                afr[m][3] = __float_as_uint(As[(row + gID + 8) * ASTRIDE + kk + tig + 4]);
            }
#pragma unroll
            for (int n = 0; n < 4; n++) {
                int col = wn * 32 + n * 8 + gID;
                bfr[n][0] = __float_as_uint(Bs[(kk + tig) * BSTRIDE + col]);
                bfr[n][1] = __float_as_uint(Bs[(kk + tig + 4) * BSTRIDE + col]);
            }
#pragma unroll
            for (int m = 0; m < 4; m++)
#pragma unroll
                for (int n = 0; n < 4; n++) mma_tf32(acc[m][n], afr[m], bfr[n]);
        }
        buf++; if (buf >= 3) buf -= 3;
    }

    // epilogue: bias + store to g_Y
#pragma unroll
    for (int m = 0; m < 4; m++) {
        int row0 = bm * BM + wm * 64 + m * 16 + gID;
#pragma unroll
        for (int n = 0; n < 4; n++) {
            int lcol = wn * 32 + n * 8 + tig * 2;
            int gcol = bn * BN + lcol;
            float b0 = bias[colOff + lcol], b1 = bias[colOff + lcol + 1];
            if (row0 < N_NODES) {
                float2 v = make_float2(acc[m][n][0] + b0, acc[m][n][1] + b1);
                *(float2*)&g_Y[(size_t)row0 * NCOL + gcol] = v;
            }
            int row1 = row0 + 8;
            if (row1 < N_NODES) {
                float2 v = make_float2(acc[m][n][2] + b0, acc[m][n][3] + b1);
                *(float2*)&g_Y[(size_t)row1 * NCOL + gcol] = v;
            }
        }
    }
}

// ------- K2: fused coef + gather + evolve + ReLU + column partial sums ------
__global__ __launch_bounds__(256) void k_fuse(const int* __restrict__ sub_nodes,
                                              const int* __restrict__ sub_adj) {
    __shared__ float s_cr[ROWS_PER_CHUNK][S_SUB];
    __shared__ float s_ci[ROWS_PER_CHUNK][S_SUB];
    __shared__ int   s_nb[ROWS_PER_CHUNK][S_SUB];

    const int chunk = blockIdx.y;
    const int r0 = chunk * ROWS_PER_CHUNK;
    const int t = threadIdx.x;

    if (t < ROWS_PER_CHUNK) {
        const int n = r0 + t;
        int A[S_SUB][S_SUB];
        float deg[S_SUB];
        const int* a = sub_adj + n * (S_SUB * S_SUB);
#pragma unroll
        for (int s = 0; s < S_SUB; s++) {
            int d = 0;
#pragma unroll
            for (int u = 0; u < S_SUB; u++) { A[s][u] = a[s * S_SUB + u]; d += A[s][u]; }
            deg[s] = (float)d;
        }
        float tr[S_SUB], ti[S_SUB], rr[S_SUB], ri[S_SUB];
#pragma unroll
        for (int u = 0; u < S_SUB; u++) { tr[u] = (u == 0) ? 1.f : 0.f; ti[u] = 0.f; rr[u] = tr[u]; ri[u] = 0.f; }
#pragma unroll
        for (int k = 1; k <= 4; k++) {
            float nr[S_SUB], ni[S_SUB];
            float invk = 1.0f / (float)k;
#pragma unroll
            for (int u = 0; u < S_SUB; u++) {
                float sr = 0.f, si = 0.f;
#pragma unroll
                for (int s = 0; s < S_SUB; s++) {
                    float L = ((s == u) ? deg[s] : 0.f) - (float)A[s][u];
                    float m = A_COEF * L;
                    sr += m * ti[s];
                    si -= m * tr[s];
                }
                nr[u] = sr * invk; ni[u] = si * invk;
            }
#pragma unroll
            for (int u = 0; u < S_SUB; u++) { tr[u] = nr[u]; ti[u] = ni[u]; rr[u] += nr[u]; ri[u] += ni[u]; }
        }
        const int* sn = sub_nodes + n * S_SUB;
#pragma unroll
        for (int u = 0; u < S_SUB; u++) {
            s_cr[t][u] = rr[u]; s_ci[t][u] = ri[u]; s_nb[t][u] = sn[u];
        }
    }
    __syncthreads();

    const int col = blockIdx.x * 256 + t;      // [0, 512)
    float sum_r = 0.f, sq_r = 0.f, sum_i = 0.f, sq_i = 0.f;

#pragma unroll 2
    for (int r = 0; r < ROWS_PER_CHUNK; r++) {
        float ar = 0.f, ai = 0.f;
#pragma unroll
        for (int s = 0; s < S_SUB; s++) {
            const float* yrow = &g_Y[(size_t)s_nb[r][s] * NCOL];
            float yr = yrow[col];
            float yi = yrow[F_DIM + col];
            float c_r = s_cr[r][s], c_i = s_ci[r][s];
            ar += c_r * yr - c_i * yi;
            ai += c_r * yi + c_i * yr;
        }
        ar = fmaxf(ar, 0.f); ai = fmaxf(ai, 0.f);
        const int n = r0 + r;
        g_Z[(size_t)n * NCOL + col] = ar;
        g_Z[(size_t)n * NCOL + F_DIM + col] = ai;
        sum_r += ar; sq_r += ar * ar;
        sum_i += ai; sq_i += ai * ai;
    }
    g_Psum[chunk * NCOL + col] = sum_r;
    g_Psq [chunk * NCOL + col] = sq_r;
    g_Psum[chunk * NCOL + F_DIM + col] = sum_i;
    g_Psq [chunk * NCOL + F_DIM + col] = sq_i;
}

// ---------------- K3: finalize mean/var -> fold gamma/beta ------------------
__global__ void k_colfin(const float* __restrict__ gr, const float* __restrict__ br,
                         const float* __restrict__ gi, const float* __restrict__ bi) {
    const int f = blockIdx.x * 128 + threadIdx.x;   // 8 blocks x 128 = 1024
    float s = 0.f, ss = 0.f;
    for (int c = 0; c < CHUNKS; c++) { s += g_Psum[c * NCOL + f]; ss += g_Psq[c * NCOL + f]; }
    const float invN = 1.0f / (float)N_NODES;
    float mean = s * invN;
    float var  = ss * invN - mean * mean;
    float inv  = rsqrtf(var + BN_EPS);
    float gamma = (f < F_DIM) ? gr[f] : gi[f - F_DIM];
    float beta  = (f < F_DIM) ? br[f] : bi[f - F_DIM];
    g_scale[f] = gamma * inv;
    g_shift[f] = beta - mean * gamma * inv;
}

// ---------------- K4: normalize + residual + write output -------------------
__global__ __launch_bounds__(512) void k_out(const float* __restrict__ X, float* __restrict__ out) {
    const int total = N_NODES * (NCOL / 4);
    for (int i = blockIdx.x * blockDim.x + threadIdx.x; i < total; i += gridDim.x * blockDim.x) {
        int row = i >> 8;          // NCOL/4 = 256 float4 per row
        int q   = i & 255;
        float4 z = *(const float4*)&g_Z[(size_t)i * 4];
        float4 sc = *(const float4*)&g_scale[q * 4];
        float4 sh = *(const float4*)&g_shift[q * 4];
        float4 r;
        r.x = z.x * sc.x + sh.x;
        r.y = z.y * sc.y + sh.y;
        r.z = z.z * sc.z + sh.z;
        r.w = z.w * sc.w + sh.w;
        if (q < 128) {  // real half: residual +x
            float4 xv = *(const float4*)&X[(size_t)row * F_DIM + q * 4];
            r.x += xv.x; r.y += xv.y; r.z += xv.z; r.w += xv.w;
        }
        *(float4*)&out[(size_t)i * 4] = r;
    }
}

// ---------------- launch ----------------------------------------------------
extern "C" void kernel_launch(void* const* d_in, const int* in_sizes, int n_in,
                              void* d_out, int out_size) {
    const float* x        = (const float*)d_in[0];
    const int*   sub_nodes= (const int*)  d_in[2];
    const int*   sub_adj  = (const int*)  d_in[3];
    const float* Wre      = (const float*)d_in[4];
    const float* Wim      = (const float*)d_in[5];
    const float* bre      = (const float*)d_in[6];
    const float* bim      = (const float*)d_in[7];
    const float* gr       = (const float*)d_in[8];
    const float* br       = (const float*)d_in[9];
    const float* gi       = (const float*)d_in[10];
    const float* bi       = (const float*)d_in[11];
    float* out = (float*)d_out;

    static bool attr_done = false;
    if (!attr_done) {
        cudaFuncSetAttribute(k_gemm, cudaFuncAttributeMaxDynamicSharedMemorySize, GEMM_SMEM);
        attr_done = true;
    }

    k_prep<<<592, 256>>>(x, Wre, Wim);
    dim3 ggrid((N_NODES + BM - 1) / BM, NCOL / BN);
    k_gemm<<<ggrid, 256, GEMM_SMEM>>>(bre, bim);
    k_fuse<<<dim3(2, CHUNKS), 256>>>(sub_nodes, sub_adj);
    k_colfin<<<8, 128>>>(gr, br, gi, bi);
    k_out<<<640, 512>>>(x, out);
}